// round 4
// baseline (speedup 1.0000x reference)
#include <cuda_runtime.h>

// GriddingReverse: grid [B,128,128,128] fp32 -> ptcloud [B, 128^3, 3] fp32.
//
// Round-3 = Round-2 resubmit (infra failure, no data).
// Strategy (L1/LSU-bound per Round-1 ncu, NOT DRAM-bound):
//   - one warp per (b, x, y-segment of 8); lane t owns z in [4t, 4t+4)
//   - register-carried y-sweep: rows (x-1,y-1),(x,y-1) are kept in registers
//     from the previous iteration, so each output row costs only 2 new
//     LDG.128 per thread (vs 4 in round 1) -> ~0.72x L1 wavefronts
//   - z-1 neighbor of each thread's first point via __shfl_up (1 per loaded row)
//   - 3 aligned STG.128 per thread per row (unchanged, already coalesced)

#define S 128
#define SEG 8
#define EPSF 1e-6f

__global__ void __launch_bounds__(256)
gridding_reverse_sweep(const float4* __restrict__ g4,
                       float4* __restrict__ out4,
                       int nwarps)
{
    const int gtid = blockIdx.x * blockDim.x + threadIdx.x;
    const int w = gtid >> 5;
    const int t = gtid & 31;
    if (w >= nwarps) return;

    // w = ((b*128 + x)*16 + seg)
    const int seg = w & 15;
    const int x   = (w >> 4) & (S - 1);
    const int b   = w >> 11;
    const int y0  = seg << 3;

    const int rowOut = (b * S + x) * S;     // + y gives output row id
    const float4 z4 = make_float4(0.f, 0.f, 0.f, 0.f);

    if (x == 0) {                            // whole x==0 plane is zeros
#pragma unroll
        for (int i = 0; i < SEG; ++i) {
            const int ob = (rowOut + y0 + i) * 96 + t * 3;
            out4[ob] = z4; out4[ob + 1] = z4; out4[ob + 2] = z4;
        }
        return;
    }

    int y = y0;
    if (y0 == 0) {                           // y==0 row is zeros
        const int ob = rowOut * 96 + t * 3;
        out4[ob] = z4; out4[ob + 1] = z4; out4[ob + 2] = z4;
        y = 1;
    }
    const int yend = y0 + SEG;

    // grid row bases in float4 units: row (b, X, Y) starts at ((b*S+X)*S+Y)*32
    const int gbA = ((b * S + (x - 1)) * S) * 32;   // (x-1, y) rows
    const int gbB = gbA + S * 32;                   // (x,   y) rows

    // initial carried rows at y-1
    float4 hA = g4[gbA + (y - 1) * 32 + t];
    float4 hB = g4[gbB + (y - 1) * 32 + t];
    float  aA = __shfl_up_sync(0xffffffffu, hA.w, 1);
    float  aB = __shfl_up_sync(0xffffffffu, hB.w, 1);

    const float xf = (float)x;
    const float xm = xf - 1.0f;
    const float sc = 2.0f / (float)S;       // 0.015625
    const float zbase = (float)(t * 4);

    for (; y < yend; ++y) {
        const float4 hC = g4[gbA + y * 32 + t];
        const float4 hD = g4[gbB + y * 32 + t];
        const float aC = __shfl_up_sync(0xffffffffu, hC.w, 1);
        const float aD = __shfl_up_sync(0xffffffffu, hD.w, 1);

        const float HA[4] = {hA.x, hA.y, hA.z, hA.w};
        const float HB[4] = {hB.x, hB.y, hB.z, hB.w};
        const float HC[4] = {hC.x, hC.y, hC.z, hC.w};
        const float HD[4] = {hD.x, hD.y, hD.z, hD.w};
        const float LA[4] = {aA, hA.x, hA.y, hA.z};
        const float LB[4] = {aB, hB.x, hB.y, hB.z};
        const float LC[4] = {aC, hC.x, hC.y, hC.z};
        const float LD[4] = {aD, hD.x, hD.y, hD.z};

        const float yf = (float)y;
        const float ym = yf - 1.0f;

        float res[12];
#pragma unroll
        for (int j = 0; j < 4; ++j) {
            const float pA = LA[j] + HA[j];   // pair sum per input row
            const float pB = LB[j] + HB[j];
            const float pC = LC[j] + HC[j];
            const float pD = LD[j] + HD[j];

            const float x_lo = pA + pC;       // dx = 0 rows
            const float x_hi = pB + pD;       // dx = 1 rows
            const float y_lo = pA + pB;       // dy = 0 rows
            const float y_hi = pC + pD;       // dy = 1 rows
            const float z_lo = (LA[j] + LB[j]) + (LC[j] + LD[j]);
            const float z_hi = (HA[j] + HB[j]) + (HC[j] + HD[j]);

            const float wsum = x_lo + x_hi + EPSF;
            const float inv  = __fdividef(1.0f, wsum);
            const float zf   = zbase + (float)j;

            float px = ((x_hi * xf + x_lo * xm) * inv - 64.0f) * sc;
            float py = ((y_hi * yf + y_lo * ym) * inv - 64.0f) * sc;
            float pz = ((z_hi * zf + z_lo * (zf - 1.0f)) * inv - 64.0f) * sc;

            if (t == 0 && j == 0) { px = 0.f; py = 0.f; pz = 0.f; }  // z==0

            res[j * 3 + 0] = px;
            res[j * 3 + 1] = py;
            res[j * 3 + 2] = pz;
        }

        const int ob = (rowOut + y) * 96 + t * 3;
        out4[ob + 0] = make_float4(res[0], res[1],  res[2],  res[3]);
        out4[ob + 1] = make_float4(res[4], res[5],  res[6],  res[7]);
        out4[ob + 2] = make_float4(res[8], res[9],  res[10], res[11]);

        hA = hC; aA = aC;
        hB = hD; aB = aD;
    }
}

extern "C" void kernel_launch(void* const* d_in, const int* in_sizes, int n_in,
                              void* d_out, int out_size)
{
    const float4* g4 = (const float4*)d_in[0];
    float4* o4 = (float4*)d_out;

    const int total = in_sizes[0];          // B * 128^3
    const int nb = total >> 21;             // B
    const int nwarps = nb * S * (S / SEG);  // one warp per (b, x, y-segment)

    const int threads = 256;
    const long long nthreads = (long long)nwarps * 32;
    const int blocks = (int)((nthreads + threads - 1) / threads);

    gridding_reverse_sweep<<<blocks, threads>>>(g4, o4, nwarps);
}

// round 5
// speedup vs baseline: 1.0024x; 1.0024x over previous
#include <cuda_runtime.h>

// GriddingReverse: grid [B,128,128,128] fp32 -> ptcloud [B, 128^3, 3] fp32.
//
// Round-3 = Round-2 resubmit (infra failure, no data).
// Strategy (L1/LSU-bound per Round-1 ncu, NOT DRAM-bound):
//   - one warp per (b, x, y-segment of 8); lane t owns z in [4t, 4t+4)
//   - register-carried y-sweep: rows (x-1,y-1),(x,y-1) are kept in registers
//     from the previous iteration, so each output row costs only 2 new
//     LDG.128 per thread (vs 4 in round 1) -> ~0.72x L1 wavefronts
//   - z-1 neighbor of each thread's first point via __shfl_up (1 per loaded row)
//   - 3 aligned STG.128 per thread per row (unchanged, already coalesced)

#define S 128
#define SEG 8
#define EPSF 1e-6f

__global__ void __launch_bounds__(256)
gridding_reverse_sweep(const float4* __restrict__ g4,
                       float4* __restrict__ out4,
                       int nwarps)
{
    const int gtid = blockIdx.x * blockDim.x + threadIdx.x;
    const int w = gtid >> 5;
    const int t = gtid & 31;
    if (w >= nwarps) return;

    // w = ((b*128 + x)*16 + seg)
    const int seg = w & 15;
    const int x   = (w >> 4) & (S - 1);
    const int b   = w >> 11;
    const int y0  = seg << 3;

    const int rowOut = (b * S + x) * S;     // + y gives output row id
    const float4 z4 = make_float4(0.f, 0.f, 0.f, 0.f);

    if (x == 0) {                            // whole x==0 plane is zeros
#pragma unroll
        for (int i = 0; i < SEG; ++i) {
            const int ob = (rowOut + y0 + i) * 96 + t * 3;
            out4[ob] = z4; out4[ob + 1] = z4; out4[ob + 2] = z4;
        }
        return;
    }

    int y = y0;
    if (y0 == 0) {                           // y==0 row is zeros
        const int ob = rowOut * 96 + t * 3;
        out4[ob] = z4; out4[ob + 1] = z4; out4[ob + 2] = z4;
        y = 1;
    }
    const int yend = y0 + SEG;

    // grid row bases in float4 units: row (b, X, Y) starts at ((b*S+X)*S+Y)*32
    const int gbA = ((b * S + (x - 1)) * S) * 32;   // (x-1, y) rows
    const int gbB = gbA + S * 32;                   // (x,   y) rows

    // initial carried rows at y-1
    float4 hA = g4[gbA + (y - 1) * 32 + t];
    float4 hB = g4[gbB + (y - 1) * 32 + t];
    float  aA = __shfl_up_sync(0xffffffffu, hA.w, 1);
    float  aB = __shfl_up_sync(0xffffffffu, hB.w, 1);

    const float xf = (float)x;
    const float xm = xf - 1.0f;
    const float sc = 2.0f / (float)S;       // 0.015625
    const float zbase = (float)(t * 4);

    for (; y < yend; ++y) {
        const float4 hC = g4[gbA + y * 32 + t];
        const float4 hD = g4[gbB + y * 32 + t];
        const float aC = __shfl_up_sync(0xffffffffu, hC.w, 1);
        const float aD = __shfl_up_sync(0xffffffffu, hD.w, 1);

        const float HA[4] = {hA.x, hA.y, hA.z, hA.w};
        const float HB[4] = {hB.x, hB.y, hB.z, hB.w};
        const float HC[4] = {hC.x, hC.y, hC.z, hC.w};
        const float HD[4] = {hD.x, hD.y, hD.z, hD.w};
        const float LA[4] = {aA, hA.x, hA.y, hA.z};
        const float LB[4] = {aB, hB.x, hB.y, hB.z};
        const float LC[4] = {aC, hC.x, hC.y, hC.z};
        const float LD[4] = {aD, hD.x, hD.y, hD.z};

        const float yf = (float)y;
        const float ym = yf - 1.0f;

        float res[12];
#pragma unroll
        for (int j = 0; j < 4; ++j) {
            const float pA = LA[j] + HA[j];   // pair sum per input row
            const float pB = LB[j] + HB[j];
            const float pC = LC[j] + HC[j];
            const float pD = LD[j] + HD[j];

            const float x_lo = pA + pC;       // dx = 0 rows
            const float x_hi = pB + pD;       // dx = 1 rows
            const float y_lo = pA + pB;       // dy = 0 rows
            const float y_hi = pC + pD;       // dy = 1 rows
            const float z_lo = (LA[j] + LB[j]) + (LC[j] + LD[j]);
            const float z_hi = (HA[j] + HB[j]) + (HC[j] + HD[j]);

            const float wsum = x_lo + x_hi + EPSF;
            const float inv  = __fdividef(1.0f, wsum);
            const float zf   = zbase + (float)j;

            float px = ((x_hi * xf + x_lo * xm) * inv - 64.0f) * sc;
            float py = ((y_hi * yf + y_lo * ym) * inv - 64.0f) * sc;
            float pz = ((z_hi * zf + z_lo * (zf - 1.0f)) * inv - 64.0f) * sc;

            if (t == 0 && j == 0) { px = 0.f; py = 0.f; pz = 0.f; }  // z==0

            res[j * 3 + 0] = px;
            res[j * 3 + 1] = py;
            res[j * 3 + 2] = pz;
        }

        const int ob = (rowOut + y) * 96 + t * 3;
        out4[ob + 0] = make_float4(res[0], res[1],  res[2],  res[3]);
        out4[ob + 1] = make_float4(res[4], res[5],  res[6],  res[7]);
        out4[ob + 2] = make_float4(res[8], res[9],  res[10], res[11]);

        hA = hC; aA = aC;
        hB = hD; aB = aD;
    }
}

extern "C" void kernel_launch(void* const* d_in, const int* in_sizes, int n_in,
                              void* d_out, int out_size)
{
    const float4* g4 = (const float4*)d_in[0];
    float4* o4 = (float4*)d_out;

    const int total = in_sizes[0];          // B * 128^3
    const int nb = total >> 21;             // B
    const int nwarps = nb * S * (S / SEG);  // one warp per (b, x, y-segment)

    const int threads = 256;
    const long long nthreads = (long long)nwarps * 32;
    const int blocks = (int)((nthreads + threads - 1) / threads);

    gridding_reverse_sweep<<<blocks, threads>>>(g4, o4, nwarps);
}

// round 6
// speedup vs baseline: 1.2086x; 1.2057x over previous
#include <cuda_runtime.h>

// GriddingReverse: grid [B,128,128,128] fp32 -> ptcloud [B, 128^3, 3] fp32.
//
// Round-6: revert to the flat Round-1 structure (best: 32.8us). Round-5's
// y-sweep cut L1 wavefronts but REGRESSED (39.6us) -> kernel is latency/
// occupancy-bound, not L1-throughput-bound. So: maximize warps in flight.
//   - one warp per (b, x, y) row; lane t owns z in [4t, 4t+4)
//   - 4 independent LDG.128 per thread (max MLP), z-1 neighbor via shfl_up
//   - 3 aligned STG.128 per thread
//   - __launch_bounds__(256, 8): cap 32 regs -> 64 warps/SM theoretical occ
//   - __fdividef: shortens the per-point critical path

#define S 128
#define EPSF 1e-6f

__global__ void __launch_bounds__(256, 8)
gridding_reverse_kernel(const float4* __restrict__ g4,
                        float4* __restrict__ out4,
                        int nrows)
{
    const int gtid = blockIdx.x * blockDim.x + threadIdx.x;
    const int w = gtid >> 5;   // row id: b*128*128 + x*128 + y
    const int t = gtid & 31;   // lane == z-group (4 points)
    if (w >= nrows) return;

    const int y = w & (S - 1);
    const int x = (w >> 7) & (S - 1);
    const int b = w >> 14;

    const int outBase = w * 96 + t * 3;  // float4 index into output

    if (x == 0 || y == 0) {
        const float4 z4 = make_float4(0.f, 0.f, 0.f, 0.f);
        out4[outBase + 0] = z4;
        out4[outBase + 1] = z4;
        out4[outBase + 2] = z4;
        return;
    }

    // Row base in float4 units: row (b, X, Y) = ((b*S + X)*S + Y) * (S/4)
    const int base = ((b * S + (x - 1)) * S + (y - 1)) * (S / 4);
    const float4* __restrict__ r00 = g4 + base;                 // (x-1, y-1)
    const float4* __restrict__ r01 = r00 + (S / 4);             // (x-1, y  )
    const float4* __restrict__ r10 = r00 + S * (S / 4);         // (x  , y-1)
    const float4* __restrict__ r11 = r10 + (S / 4);             // (x  , y  )

    const float4 B00 = r00[t];
    const float4 B01 = r01[t];
    const float4 B10 = r10[t];
    const float4 B11 = r11[t];

    // z-1 value for point j=0 is lane (t-1)'s .w. Lane 0's first point is the
    // z==0 boundary so its (garbage) shuffle input is unused.
    const float a00 = __shfl_up_sync(0xffffffffu, B00.w, 1);
    const float a01 = __shfl_up_sync(0xffffffffu, B01.w, 1);
    const float a10 = __shfl_up_sync(0xffffffffu, B10.w, 1);
    const float a11 = __shfl_up_sync(0xffffffffu, B11.w, 1);

    const float hi00[4] = {B00.x, B00.y, B00.z, B00.w};
    const float hi01[4] = {B01.x, B01.y, B01.z, B01.w};
    const float hi10[4] = {B10.x, B10.y, B10.z, B10.w};
    const float hi11[4] = {B11.x, B11.y, B11.z, B11.w};
    const float lo00[4] = {a00, B00.x, B00.y, B00.z};
    const float lo01[4] = {a01, B01.x, B01.y, B01.z};
    const float lo10[4] = {a10, B10.x, B10.y, B10.z};
    const float lo11[4] = {a11, B11.x, B11.y, B11.z};

    const float xf = (float)x;
    const float yf = (float)y;
    const float zf0 = (float)(t * 4);
    const float scale = 2.0f / (float)S;     // 0.015625
    const float half = (float)S * 0.5f;      // 64

    float res[12];

#pragma unroll
    for (int j = 0; j < 4; ++j) {
        const float p00 = lo00[j] + hi00[j];
        const float p01 = lo01[j] + hi01[j];
        const float p10 = lo10[j] + hi10[j];
        const float p11 = lo11[j] + hi11[j];

        const float x_lo = p00 + p01;               // dx = 0 rows
        const float x_hi = p10 + p11;               // dx = 1 rows
        const float y_lo = p00 + p10;               // dy = 0
        const float y_hi = p01 + p11;               // dy = 1
        const float z_lo = (lo00[j] + lo01[j]) + (lo10[j] + lo11[j]);
        const float z_hi = (hi00[j] + hi01[j]) + (hi10[j] + hi11[j]);

        const float wsum = x_lo + x_hi + EPSF;
        const float inv = __fdividef(1.0f, wsum);

        const float zf = zf0 + (float)j;

        float px = ((x_hi * xf + x_lo * (xf - 1.0f)) * inv - half) * scale;
        float py = ((y_hi * yf + y_lo * (yf - 1.0f)) * inv - half) * scale;
        float pz = ((z_hi * zf + z_lo * (zf - 1.0f)) * inv - half) * scale;

        if (t == 0 && j == 0) { px = 0.f; py = 0.f; pz = 0.f; }  // z==0 boundary

        res[j * 3 + 0] = px;
        res[j * 3 + 1] = py;
        res[j * 3 + 2] = pz;
    }

    out4[outBase + 0] = make_float4(res[0], res[1], res[2], res[3]);
    out4[outBase + 1] = make_float4(res[4], res[5], res[6], res[7]);
    out4[outBase + 2] = make_float4(res[8], res[9], res[10], res[11]);
}

extern "C" void kernel_launch(void* const* d_in, const int* in_sizes, int n_in,
                              void* d_out, int out_size)
{
    const float4* g4 = (const float4*)d_in[0];
    float4* o4 = (float4*)d_out;

    const int total = in_sizes[0];          // B * 128^3
    const int nb = total >> 21;             // B
    const int nrows = nb * S * S;           // one warp per (b, x, y) row

    const int threads = 256;
    const long long nthreads = (long long)nrows * 32;
    const int blocks = (int)((nthreads + threads - 1) / threads);

    gridding_reverse_kernel<<<blocks, threads>>>(g4, o4, nrows);
}

// round 7
// speedup vs baseline: 1.3641x; 1.1287x over previous
#include <cuda_runtime.h>

// GriddingReverse: grid [B,128,128,128] fp32 -> ptcloud [B, 128^3, 3] fp32.
//
// Round-7: the binding resource was identified as L2 sector traffic from
// NON-COALESCED stores: lane t wrote out4[base + 3t + k] (48B lane stride),
// so each STG.128 spanned 12 cache lines and ~3x the sector transactions
// (odd lanes straddle 32B sectors). ~300MB of L2 store traffic for a 100MB
// output == the observed ~32us wall across all prior variants.
// Fix: stage each warp's 96 float4 results in shared memory (conflict-free),
// then store fully coalesced (unit-stride STG.128, 4 wavefronts each).
//   - one warp per (b, x, y) row; lane t computes z in [4t, 4t+4)
//   - 4 independent LDG.128 per thread, z-1 neighbor via shfl_up
//   - 3 STS.128 (48B stride, conflict-free phases) + syncwarp + 3 LDS.128
//     (contiguous) + 3 coalesced STG.128

#define S 128
#define EPSF 1e-6f

__global__ void __launch_bounds__(256, 8)
gridding_reverse_kernel(const float4* __restrict__ g4,
                        float4* __restrict__ out4,
                        int nrows)
{
    __shared__ float4 stage[8][96];          // 12 KB: per-warp transpose buffer

    const int gtid = blockIdx.x * blockDim.x + threadIdx.x;
    const int w = gtid >> 5;   // row id: b*128*128 + x*128 + y
    const int t = gtid & 31;   // lane == z-group (4 points)
    if (w >= nrows) return;

    const int y = w & (S - 1);
    const int x = (w >> 7) & (S - 1);
    const int b = w >> 14;

    const int outBase = w * 96;              // float4 index of this row's output

    if (x == 0 || y == 0) {                  // boundary rows: zeros, coalesced
        const float4 z4 = make_float4(0.f, 0.f, 0.f, 0.f);
        out4[outBase + t]      = z4;
        out4[outBase + 32 + t] = z4;
        out4[outBase + 64 + t] = z4;
        return;
    }

    // Row base in float4 units: row (b, X, Y) = ((b*S + X)*S + Y) * (S/4)
    const int base = ((b * S + (x - 1)) * S + (y - 1)) * (S / 4);
    const float4* __restrict__ r00 = g4 + base;                 // (x-1, y-1)
    const float4* __restrict__ r01 = r00 + (S / 4);             // (x-1, y  )
    const float4* __restrict__ r10 = r00 + S * (S / 4);         // (x  , y-1)
    const float4* __restrict__ r11 = r10 + (S / 4);             // (x  , y  )

    const float4 B00 = r00[t];
    const float4 B01 = r01[t];
    const float4 B10 = r10[t];
    const float4 B11 = r11[t];

    // z-1 value for point j=0 is lane (t-1)'s .w. Lane 0's first point is the
    // z==0 boundary so its (garbage) shuffle input is unused.
    const float a00 = __shfl_up_sync(0xffffffffu, B00.w, 1);
    const float a01 = __shfl_up_sync(0xffffffffu, B01.w, 1);
    const float a10 = __shfl_up_sync(0xffffffffu, B10.w, 1);
    const float a11 = __shfl_up_sync(0xffffffffu, B11.w, 1);

    const float hi00[4] = {B00.x, B00.y, B00.z, B00.w};
    const float hi01[4] = {B01.x, B01.y, B01.z, B01.w};
    const float hi10[4] = {B10.x, B10.y, B10.z, B10.w};
    const float hi11[4] = {B11.x, B11.y, B11.z, B11.w};
    const float lo00[4] = {a00, B00.x, B00.y, B00.z};
    const float lo01[4] = {a01, B01.x, B01.y, B01.z};
    const float lo10[4] = {a10, B10.x, B10.y, B10.z};
    const float lo11[4] = {a11, B11.x, B11.y, B11.z};

    const float xf = (float)x;
    const float yf = (float)y;
    const float zf0 = (float)(t * 4);
    const float scale = 2.0f / (float)S;     // 0.015625
    const float half = (float)S * 0.5f;      // 64

    float res[12];

#pragma unroll
    for (int j = 0; j < 4; ++j) {
        const float p00 = lo00[j] + hi00[j];
        const float p01 = lo01[j] + hi01[j];
        const float p10 = lo10[j] + hi10[j];
        const float p11 = lo11[j] + hi11[j];

        const float x_lo = p00 + p01;               // dx = 0 rows
        const float x_hi = p10 + p11;               // dx = 1 rows
        const float y_lo = p00 + p10;               // dy = 0
        const float y_hi = p01 + p11;               // dy = 1
        const float z_lo = (lo00[j] + lo01[j]) + (lo10[j] + lo11[j]);
        const float z_hi = (hi00[j] + hi01[j]) + (hi10[j] + hi11[j]);

        const float wsum = x_lo + x_hi + EPSF;
        const float inv = __fdividef(1.0f, wsum);

        const float zf = zf0 + (float)j;

        float px = ((x_hi * xf + x_lo * (xf - 1.0f)) * inv - half) * scale;
        float py = ((y_hi * yf + y_lo * (yf - 1.0f)) * inv - half) * scale;
        float pz = ((z_hi * zf + z_lo * (zf - 1.0f)) * inv - half) * scale;

        if (t == 0 && j == 0) { px = 0.f; py = 0.f; pz = 0.f; }  // z==0 boundary

        res[j * 3 + 0] = px;
        res[j * 3 + 1] = py;
        res[j * 3 + 2] = pz;
    }

    // ── warp-local transpose: strided STS (conflict-free), coalesced STG ──
    float4* s = stage[threadIdx.x >> 5];
    s[t * 3 + 0] = make_float4(res[0], res[1],  res[2],  res[3]);
    s[t * 3 + 1] = make_float4(res[4], res[5],  res[6],  res[7]);
    s[t * 3 + 2] = make_float4(res[8], res[9],  res[10], res[11]);
    __syncwarp();

    out4[outBase + t]      = s[t];
    out4[outBase + 32 + t] = s[32 + t];
    out4[outBase + 64 + t] = s[64 + t];
}

extern "C" void kernel_launch(void* const* d_in, const int* in_sizes, int n_in,
                              void* d_out, int out_size)
{
    const float4* g4 = (const float4*)d_in[0];
    float4* o4 = (float4*)d_out;

    const int total = in_sizes[0];          // B * 128^3
    const int nb = total >> 21;             // B
    const int nrows = nb * S * S;           // one warp per (b, x, y) row

    const int threads = 256;
    const long long nthreads = (long long)nrows * 32;
    const int blocks = (int)((nthreads + threads - 1) / threads);

    gridding_reverse_kernel<<<blocks, threads>>>(g4, o4, nrows);
}

// round 9
// speedup vs baseline: 1.4868x; 1.0899x over previous
#include <cuda_runtime.h>
#include <cstdint>

// GriddingReverse: grid [B,128,128,128] fp32 -> ptcloud [B, 128^3, 3] fp32.
//
// Round-9 = Round-8 resubmit (missing <cstdint> include; no perf data).
// R7 (smem-coalesced stores) won 32.8->29.1us, but the STS+LDS+STG back-end
// is 36 of the 52 L1TEX wavefronts per warp. Replace LDS+STG with a single
// block-wide cp.async.bulk (shared -> global, 12KB contiguous): the TMA
// engine drains the staged block, removing 24 wf + ~7 instrs per warp from
// the SM-side path. Per-warp SM work: 16 LDG wf + 12 STS wf only.
//   - block = 8 warps = 8 consecutive (b,x,y) rows; lane t owns z in [4t,4t+4)
//   - 4 independent LDG.128 per thread, z-1 neighbor via shfl_up
//   - results staged to smem (48B-stride STS.128, conflict-free phases)
//   - boundary rows stage zeros (uniform control flow for __syncthreads)
//   - one thread: fence.proxy.async -> cp.async.bulk 12288B -> commit -> wait

#define S 128
#define EPSF 1e-6f

__global__ void __launch_bounds__(256, 8)
gridding_reverse_kernel(const float4* __restrict__ g4,
                        float4* __restrict__ out4)
{
    __shared__ __align__(16) float4 stage[768];   // 8 rows * 96 float4 = 12KB

    const int tid = threadIdx.x;
    const int t   = tid & 31;                     // lane == z-group (4 points)
    const int wid = tid >> 5;
    const int w   = blockIdx.x * 8 + wid;         // row id: b*128*128 + x*128 + y

    const int y = w & (S - 1);
    const int x = (w >> 7) & (S - 1);
    const int b = w >> 14;

    float4* s = &stage[wid * 96];

    if (x == 0 || y == 0) {
        // boundary row: stage zeros (keep all threads alive for __syncthreads)
        const float4 z4 = make_float4(0.f, 0.f, 0.f, 0.f);
        s[t * 3 + 0] = z4;
        s[t * 3 + 1] = z4;
        s[t * 3 + 2] = z4;
    } else {
        // Row base in float4 units: row (b, X, Y) = ((b*S + X)*S + Y) * (S/4)
        const int base = ((b * S + (x - 1)) * S + (y - 1)) * (S / 4);
        const float4* __restrict__ r00 = g4 + base;             // (x-1, y-1)
        const float4* __restrict__ r01 = r00 + (S / 4);         // (x-1, y  )
        const float4* __restrict__ r10 = r00 + S * (S / 4);     // (x  , y-1)
        const float4* __restrict__ r11 = r10 + (S / 4);         // (x  , y  )

        const float4 B00 = r00[t];
        const float4 B01 = r01[t];
        const float4 B10 = r10[t];
        const float4 B11 = r11[t];

        // z-1 value for point j=0 comes from lane t-1's .w; lane 0's first
        // point is the z==0 boundary, so its garbage shuffle input is unused.
        const float a00 = __shfl_up_sync(0xffffffffu, B00.w, 1);
        const float a01 = __shfl_up_sync(0xffffffffu, B01.w, 1);
        const float a10 = __shfl_up_sync(0xffffffffu, B10.w, 1);
        const float a11 = __shfl_up_sync(0xffffffffu, B11.w, 1);

        const float hi00[4] = {B00.x, B00.y, B00.z, B00.w};
        const float hi01[4] = {B01.x, B01.y, B01.z, B01.w};
        const float hi10[4] = {B10.x, B10.y, B10.z, B10.w};
        const float hi11[4] = {B11.x, B11.y, B11.z, B11.w};
        const float lo00[4] = {a00, B00.x, B00.y, B00.z};
        const float lo01[4] = {a01, B01.x, B01.y, B01.z};
        const float lo10[4] = {a10, B10.x, B10.y, B10.z};
        const float lo11[4] = {a11, B11.x, B11.y, B11.z};

        const float xf = (float)x;
        const float yf = (float)y;
        const float zf0 = (float)(t * 4);
        const float scale = 2.0f / (float)S;     // 0.015625
        const float half = (float)S * 0.5f;      // 64

        float res[12];

#pragma unroll
        for (int j = 0; j < 4; ++j) {
            const float p00 = lo00[j] + hi00[j];
            const float p01 = lo01[j] + hi01[j];
            const float p10 = lo10[j] + hi10[j];
            const float p11 = lo11[j] + hi11[j];

            const float x_lo = p00 + p01;               // dx = 0 rows
            const float x_hi = p10 + p11;               // dx = 1 rows
            const float y_lo = p00 + p10;               // dy = 0
            const float y_hi = p01 + p11;               // dy = 1
            const float z_lo = (lo00[j] + lo01[j]) + (lo10[j] + lo11[j]);
            const float z_hi = (hi00[j] + hi01[j]) + (hi10[j] + hi11[j]);

            const float wsum = x_lo + x_hi + EPSF;
            const float inv = __fdividef(1.0f, wsum);

            const float zf = zf0 + (float)j;

            float px = ((x_hi * xf + x_lo * (xf - 1.0f)) * inv - half) * scale;
            float py = ((y_hi * yf + y_lo * (yf - 1.0f)) * inv - half) * scale;
            float pz = ((z_hi * zf + z_lo * (zf - 1.0f)) * inv - half) * scale;

            if (t == 0 && j == 0) { px = 0.f; py = 0.f; pz = 0.f; }  // z==0

            res[j * 3 + 0] = px;
            res[j * 3 + 1] = py;
            res[j * 3 + 2] = pz;
        }

        // stage (48B-stride STS.128: banks distinct within each 8-lane phase)
        s[t * 3 + 0] = make_float4(res[0], res[1],  res[2],  res[3]);
        s[t * 3 + 1] = make_float4(res[4], res[5],  res[6],  res[7]);
        s[t * 3 + 2] = make_float4(res[8], res[9],  res[10], res[11]);
    }

    __syncthreads();

    // one bulk async copy: 12KB smem -> contiguous 12KB of output
    if (tid == 0) {
        float4* dst = out4 + (size_t)blockIdx.x * 768;
        unsigned int smem_addr;
        asm("{ .reg .u64 a; cvta.to.shared.u64 a, %1; cvt.u32.u64 %0, a; }"
            : "=r"(smem_addr) : "l"(stage));
        asm volatile("fence.proxy.async.shared::cta;" ::: "memory");
        asm volatile(
            "cp.async.bulk.global.shared::cta.bulk_group [%0], [%1], %2;"
            :: "l"(dst), "r"(smem_addr), "r"(12288) : "memory");
        asm volatile("cp.async.bulk.commit_group;" ::: "memory");
        asm volatile("cp.async.bulk.wait_group 0;" ::: "memory");
    }
}

extern "C" void kernel_launch(void* const* d_in, const int* in_sizes, int n_in,
                              void* d_out, int out_size)
{
    const float4* g4 = (const float4*)d_in[0];
    float4* o4 = (float4*)d_out;

    const int total = in_sizes[0];          // B * 128^3
    const int nb = total >> 21;             // B
    const int nrows = nb * S * S;           // one warp per (b, x, y) row
    const int blocks = nrows / 8;           // 8 rows per 256-thread block

    gridding_reverse_kernel<<<blocks, 256>>>(g4, o4);
}